// round 15
// baseline (speedup 1.0000x reference)
#include <cuda_runtime.h>
#include <cstdint>

#define B 8
#define DIM 192
#define Hh 128
#define Ww 128
#define KS 7
#define PAD 3
#define HID 48
#define KK 49          // 7*7
#define PLANE (Hh*Ww)  // 16384
#define OUTW (DIM*KK)  // 9408
#define EPS 1e-5f

// -------- scratch (device globals; no allocation allowed) --------
__device__ float g_pooled[B * DIM];      // [b, c]
__device__ float g_wdyn[B * OUTW];       // [b, c*49 + k]

// -------- cp.async helpers --------
__device__ __forceinline__ void cp_async4(uint32_t saddr, const void* g, bool ok) {
    int sz = ok ? 4 : 0;
    asm volatile("cp.async.ca.shared.global [%0], [%1], 4, %2;"
                 :: "r"(saddr), "l"(g), "r"(sz));
}
__device__ __forceinline__ void cp_async16(uint32_t saddr, const void* g, bool ok) {
    int sz = ok ? 16 : 0;
    asm volatile("cp.async.cg.shared.global [%0], [%1], 16, %2;"
                 :: "r"(saddr), "l"(g), "r"(sz));
}
__device__ __forceinline__ void cp_commit() {
    asm volatile("cp.async.commit_group;");
}
__device__ __forceinline__ void cp_wait_1() {   // allow 1 group in flight
    asm volatile("cp.async.wait_group 1;");
}
__device__ __forceinline__ uint32_t smem_u32(const void* p) {
    return (uint32_t)__cvta_generic_to_shared(p);
}

// ============================================================
// Kernel 1: global average pool over HxW per (b,c) plane
// (proven R10 form: 18.9-19.1us)
// ============================================================
__global__ __launch_bounds__(256) void pool_kernel(const float* __restrict__ x) {
    int bc = blockIdx.x;
    const float4* p = reinterpret_cast<const float4*>(x + (size_t)bc * PLANE);
    float s = 0.f;
    #pragma unroll 4
    for (int i = threadIdx.x; i < PLANE / 4; i += 256) {
        float4 v = p[i];
        s += (v.x + v.y) + (v.z + v.w);
    }
    #pragma unroll
    for (int off = 16; off > 0; off >>= 1)
        s += __shfl_down_sync(0xffffffffu, s, off);
    __shared__ float red[8];
    int lane = threadIdx.x & 31, warp = threadIdx.x >> 5;
    if (lane == 0) red[warp] = s;
    __syncthreads();
    if (warp == 0) {
        float t = (lane < 8) ? red[lane] : 0.f;
        #pragma unroll
        for (int off = 4; off > 0; off >>= 1)
            t += __shfl_down_sync(0xffffffffu, t, off);
        if (lane == 0) g_pooled[bc] = t * (1.0f / (float)PLANE);
    }
}

// ============================================================
// Kernel 2 (fused): y = relu(BN(pooled @ w1^T)) per block, then
// wdyn[b, o] = y . w2[o,:] + b2[o] for a 128-wide chunk of o.
// ============================================================
#define W2_CHUNK 128
__global__ __launch_bounds__(128) void gen_wdyn_kernel(
    const float* __restrict__ w1,
    const float* __restrict__ gamma, const float* __restrict__ beta,
    const float* __restrict__ mean,  const float* __restrict__ var,
    const float* __restrict__ w2, const float* __restrict__ b2) {
    int b = blockIdx.y;
    int obase = blockIdx.x * W2_CHUNK;
    int t = threadIdx.x;

    __shared__ float sy[HID];
    __shared__ float w2s[W2_CHUNK * (HID + 1)];

    if (t < HID) {
        const float* pr = g_pooled + b * DIM;
        const float* wr = w1 + t * DIM;
        float s = 0.f;
        #pragma unroll 8
        for (int c = 0; c < DIM; c++) s = fmaf(pr[c], wr[c], s);
        s = (s - mean[t]) * rsqrtf(var[t] + EPS) * gamma[t] + beta[t];
        sy[t] = s > 0.f ? s : 0.f;
    }

    const int n_f4 = W2_CHUNK * HID / 4;
    const float4* w2v = reinterpret_cast<const float4*>(w2 + (size_t)obase * HID);
    int max_f4 = (OUTW - obase) * HID / 4;
    for (int i = t; i < n_f4; i += 128) {
        float4 v = (i < max_f4) ? w2v[i] : make_float4(0.f, 0.f, 0.f, 0.f);
        int row = i / (HID / 4);
        int col = (i % (HID / 4)) * 4;
        float* dst = &w2s[row * (HID + 1) + col];
        dst[0] = v.x; dst[1] = v.y; dst[2] = v.z; dst[3] = v.w;
    }
    __syncthreads();

    int o = obase + t;
    if (o < OUTW) {
        float acc = b2[o];
        const float* wr = &w2s[t * (HID + 1)];
        #pragma unroll
        for (int h = 0; h < HID; h++) acc = fmaf(sy[h], wr[h], acc);
        g_wdyn[(size_t)b * OUTW + o] = acc;
    }
}

// ============================================================
// Kernel 3: persistent TRIPLE-buffered depthwise 7x7 conv + bias.
// R10 compute shape (4x4 patch, 49 weights in regs, (256,2)).
// Prefetch distance 2: every tile's cp.async gets ~2 compute-tiles
// (~1600 cyc) to land; loop-top uses wait_group 1 (one group always
// in flight). Every iteration commits exactly one group (possibly
// empty) so the pending count is uniform. 62KB dynamic smem.
// ============================================================
#define STRIP 32
#define TROWS (STRIP + KS - 1)   // 38
#define TSTRIDE 136              // 544B row stride
#define COLOFF 4                 // smem col of gc=0
#define NTILES (B * DIM * (Hh / STRIP))   // 6144
#define DW_GRID 304
#define NCHUNK (TROWS * 32)      // 1216 16B chunks per tile
#define TILE_FLOATS (TROWS * TSTRIDE)     // 5168
#define DYN_SMEM (3 * TILE_FLOATS * 4)    // 62016 bytes

__device__ __forceinline__ void load_tile_async(
    float* tbuf, float* wbuf, int tile, const float* __restrict__ x) {
    int bc = tile >> 2;
    int strip = tile & 3;
    int r0 = strip * STRIP;
    int tid = threadIdx.x;

    if (tid < KK)
        cp_async4(smem_u32(wbuf + tid), &g_wdyn[(size_t)bc * KK + tid], true);

    const float* plane = x + (size_t)bc * PLANE;
    #pragma unroll
    for (int i = 0; i < 5; i++) {
        int idx = tid + i * 256;
        if (idx < NCHUNK) {
            int rr = idx >> 5;          // tile row
            int ch = idx & 31;          // 16B chunk within row
            int gr = r0 + rr - PAD;
            bool ok = (gr >= 0) && (gr < Hh);
            const float* src = ok ? (plane + (size_t)gr * Ww + ch * 4) : plane;
            cp_async16(smem_u32(tbuf + rr * TSTRIDE + COLOFF + ch * 4), src, ok);
        }
    }
}

__global__ __launch_bounds__(256, 2) void dwconv_kernel(
    const float* __restrict__ x, const float* __restrict__ bias,
    float* __restrict__ out) {
    extern __shared__ __align__(16) float tb[];     // 3 * TILE_FLOATS
    __shared__ __align__(16) float wbuf[3][52];

    int tid = threadIdx.x;
    int cg = tid & 31, rg = tid >> 5;
    int col = cg * 4;
    int rbase = rg * 4;

    // zero the permanent halo columns of all three buffers (once)
    for (int i = tid; i < 3 * TROWS * 8; i += 256) {
        int bufi = i / (TROWS * 8);
        int j = i - bufi * TROWS * 8;
        int rr = j >> 3;
        int k = j & 7;
        int cc = (k < 4) ? k : (128 + COLOFF + (k - 4));
        tb[bufi * TILE_FLOATS + rr * TSTRIDE + cc] = 0.f;
    }

    // prologue: prefetch tiles t and t+G (uniform: always commit)
    int t = blockIdx.x;
    if (t < NTILES) load_tile_async(tb, wbuf[0], t, x);
    cp_commit();
    if (t + DW_GRID < NTILES)
        load_tile_async(tb + TILE_FLOATS, wbuf[1], t + DW_GRID, x);
    cp_commit();
    int cur = 0;

    for (; t < NTILES; t += DW_GRID) {
        cp_wait_1();                    // oldest group (tile t) complete
        __syncthreads();                // all threads past prior compute

        int t2 = t + 2 * DW_GRID;
        int nb = cur + 2; if (nb >= 3) nb -= 3;
        if (t2 < NTILES) load_tile_async(tb + nb * TILE_FLOATS, wbuf[nb], t2, x);
        cp_commit();                    // exactly one group per iteration

        // ---- compute tile t from buffer cur ----
        int bc = t >> 2;
        int r0 = (t & 3) * STRIP;

        float w[KK];
        {
            const float4* wv = reinterpret_cast<const float4*>(wbuf[cur]);
            #pragma unroll
            for (int q = 0; q < 12; q++) {
                float4 f = wv[q];
                w[4 * q + 0] = f.x; w[4 * q + 1] = f.y;
                w[4 * q + 2] = f.z; w[4 * q + 3] = f.w;
            }
            w[48] = wbuf[cur][48];
        }

        float bia = __ldg(&bias[bc % DIM]);
        float acc[4][4];
        #pragma unroll
        for (int i = 0; i < 4; i++)
            #pragma unroll
            for (int j = 0; j < 4; j++) acc[i][j] = bia;

        const float* tile = tb + cur * TILE_FLOATS;
        #pragma unroll
        for (int ir = 0; ir < 4 + KS - 1; ir++) {     // 10 tile rows
            const float* tr = &tile[(rbase + ir) * TSTRIDE + col];
            float4 A = *reinterpret_cast<const float4*>(tr);
            float4 Bv = *reinterpret_cast<const float4*>(tr + 4);
            float4 Cv = *reinterpret_cast<const float4*>(tr + 8);
            float v[12] = {A.x, A.y, A.z, A.w,
                           Bv.x, Bv.y, Bv.z, Bv.w,
                           Cv.x, Cv.y, Cv.z, Cv.w};
            #pragma unroll
            for (int kh = 0; kh < KS; kh++) {
                int orr = ir - kh;
                if (orr >= 0 && orr < 4) {
                    #pragma unroll
                    for (int jj = 0; jj < 4; jj++) {
                        float s = acc[orr][jj];
                        #pragma unroll
                        for (int kw = 0; kw < KS; kw++)
                            s = fmaf(v[jj + kw + 1], w[kh * KS + kw], s);
                        acc[orr][jj] = s;
                    }
                }
            }
        }

        float* op = out + (size_t)bc * PLANE + (size_t)(r0 + rbase) * Ww + col;
        #pragma unroll
        for (int orr = 0; orr < 4; orr++)
            *reinterpret_cast<float4*>(op + (size_t)orr * Ww) =
                make_float4(acc[orr][0], acc[orr][1], acc[orr][2], acc[orr][3]);

        cur += 1; if (cur >= 3) cur -= 3;
    }
}

// ============================================================
// launch
// inputs: 0:x 1:w1 2:bn_gamma 3:bn_beta 4:bn_mean 5:bn_var 6:w2 7:b2 8:bias
// ============================================================
extern "C" void kernel_launch(void* const* d_in, const int* in_sizes, int n_in,
                              void* d_out, int out_size) {
    const float* x     = (const float*)d_in[0];
    const float* w1    = (const float*)d_in[1];
    const float* gamma = (const float*)d_in[2];
    const float* beta  = (const float*)d_in[3];
    const float* mean  = (const float*)d_in[4];
    const float* var   = (const float*)d_in[5];
    const float* w2    = (const float*)d_in[6];
    const float* b2    = (const float*)d_in[7];
    const float* bias  = (const float*)d_in[8];
    float* out = (float*)d_out;

    cudaFuncSetAttribute(dwconv_kernel,
                         cudaFuncAttributeMaxDynamicSharedMemorySize, DYN_SMEM);

    pool_kernel<<<B * DIM, 256>>>(x);
    dim3 g2((OUTW + W2_CHUNK - 1) / W2_CHUNK, B);
    gen_wdyn_kernel<<<g2, 128>>>(w1, gamma, beta, mean, var, w2, b2);
    dwconv_kernel<<<DW_GRID, 256, DYN_SMEM>>>(x, bias, out);
}

// round 17
// speedup vs baseline: 1.4676x; 1.4676x over previous
#include <cuda_runtime.h>
#include <cstdint>

#define B 8
#define DIM 192
#define Hh 128
#define Ww 128
#define KS 7
#define PAD 3
#define HID 48
#define KK 49          // 7*7
#define PLANE (Hh*Ww)  // 16384
#define OUTW (DIM*KK)  // 9408
#define EPS 1e-5f

// -------- scratch (device globals; no allocation allowed) --------
__device__ float g_pooled[B * DIM];      // [b, c]
__device__ float g_wdyn[B * OUTW];       // [b, c*49 + k]

// -------- cp.async helpers --------
__device__ __forceinline__ void cp_async4(uint32_t saddr, const void* g, bool ok) {
    int sz = ok ? 4 : 0;
    asm volatile("cp.async.ca.shared.global [%0], [%1], 4, %2;"
                 :: "r"(saddr), "l"(g), "r"(sz));
}
__device__ __forceinline__ void cp_async16(uint32_t saddr, const void* g, bool ok) {
    int sz = ok ? 16 : 0;
    asm volatile("cp.async.cg.shared.global [%0], [%1], 16, %2;"
                 :: "r"(saddr), "l"(g), "r"(sz));
}
__device__ __forceinline__ void cp_commit() {
    asm volatile("cp.async.commit_group;");
}
__device__ __forceinline__ void cp_wait_all() {
    asm volatile("cp.async.wait_group 0;");
}
__device__ __forceinline__ uint32_t smem_u32(const void* p) {
    return (uint32_t)__cvta_generic_to_shared(p);
}

// ============================================================
// Kernel 1: global average pool over HxW per (b,c) plane
// (proven form, ~19us, BW-bound)
// ============================================================
__global__ __launch_bounds__(256) void pool_kernel(const float* __restrict__ x) {
    int bc = blockIdx.x;
    const float4* p = reinterpret_cast<const float4*>(x + (size_t)bc * PLANE);
    float s = 0.f;
    #pragma unroll 4
    for (int i = threadIdx.x; i < PLANE / 4; i += 256) {
        float4 v = p[i];
        s += (v.x + v.y) + (v.z + v.w);
    }
    #pragma unroll
    for (int off = 16; off > 0; off >>= 1)
        s += __shfl_down_sync(0xffffffffu, s, off);
    __shared__ float red[8];
    int lane = threadIdx.x & 31, warp = threadIdx.x >> 5;
    if (lane == 0) red[warp] = s;
    __syncthreads();
    if (warp == 0) {
        float t = (lane < 8) ? red[lane] : 0.f;
        #pragma unroll
        for (int off = 4; off > 0; off >>= 1)
            t += __shfl_down_sync(0xffffffffu, t, off);
        if (lane == 0) g_pooled[bc] = t * (1.0f / (float)PLANE);
    }
}

// ============================================================
// Kernel 2 (fused): y = relu(BN(pooled @ w1^T)) per block, then
// wdyn[b, o] = y . w2[o,:] + b2[o] for a 128-wide chunk of o.
// ============================================================
#define W2_CHUNK 128
__global__ __launch_bounds__(128) void gen_wdyn_kernel(
    const float* __restrict__ w1,
    const float* __restrict__ gamma, const float* __restrict__ beta,
    const float* __restrict__ mean,  const float* __restrict__ var,
    const float* __restrict__ w2, const float* __restrict__ b2) {
    int b = blockIdx.y;
    int obase = blockIdx.x * W2_CHUNK;
    int t = threadIdx.x;

    __shared__ float sy[HID];
    __shared__ float w2s[W2_CHUNK * (HID + 1)];

    if (t < HID) {
        const float* pr = g_pooled + b * DIM;
        const float* wr = w1 + t * DIM;
        float s = 0.f;
        #pragma unroll 8
        for (int c = 0; c < DIM; c++) s = fmaf(pr[c], wr[c], s);
        s = (s - mean[t]) * rsqrtf(var[t] + EPS) * gamma[t] + beta[t];
        sy[t] = s > 0.f ? s : 0.f;
    }

    const int n_f4 = W2_CHUNK * HID / 4;
    const float4* w2v = reinterpret_cast<const float4*>(w2 + (size_t)obase * HID);
    int max_f4 = (OUTW - obase) * HID / 4;
    for (int i = t; i < n_f4; i += 128) {
        float4 v = (i < max_f4) ? w2v[i] : make_float4(0.f, 0.f, 0.f, 0.f);
        int row = i / (HID / 4);
        int col = (i % (HID / 4)) * 4;
        float* dst = &w2s[row * (HID + 1) + col];
        dst[0] = v.x; dst[1] = v.y; dst[2] = v.z; dst[3] = v.w;
    }
    __syncthreads();

    int o = obase + t;
    if (o < OUTW) {
        float acc = b2[o];
        const float* wr = &w2s[t * (HID + 1)];
        #pragma unroll
        for (int h = 0; h < HID; h++) acc = fmaf(sy[h], wr[h], acc);
        g_wdyn[(size_t)b * OUTW + o] = acc;
    }
}

// ============================================================
// Kernel 3: persistent double-buffered depthwise 7x7 conv + bias.
// Exact R10 champion shape: 4x4 patch, 49 weights in regs, (256,2),
// static 304-block schedule, distance-1 double buffer, static smem.
// Micro-fix: per-tile bias rides in the weights' cp.async group
// (wbuf slot 49) instead of a per-tile LDG.
// ============================================================
#define STRIP 32
#define TROWS (STRIP + KS - 1)   // 38
#define TSTRIDE 136              // 544B row stride
#define COLOFF 4                 // smem col of gc=0
#define NTILES (B * DIM * (Hh / STRIP))   // 6144
#define DW_GRID 304
#define NCHUNK (TROWS * 32)      // 1216 16B chunks per tile

__device__ __forceinline__ void load_tile_async(
    float* tbuf, float* wbuf, int tile,
    const float* __restrict__ x, const float* __restrict__ bias) {
    int bc = tile >> 2;
    int strip = tile & 3;
    int r0 = strip * STRIP;
    int tid = threadIdx.x;

    if (tid < KK + 1) {
        const float* src = (tid < KK) ? &g_wdyn[(size_t)bc * KK + tid]
                                      : &bias[bc % DIM];
        cp_async4(smem_u32(wbuf + tid), src, true);
    }

    const float* plane = x + (size_t)bc * PLANE;
    #pragma unroll
    for (int i = 0; i < 5; i++) {
        int idx = tid + i * 256;
        if (idx < NCHUNK) {
            int rr = idx >> 5;          // tile row
            int ch = idx & 31;          // 16B chunk within row
            int gr = r0 + rr - PAD;
            bool ok = (gr >= 0) && (gr < Hh);
            const float* src = ok ? (plane + (size_t)gr * Ww + ch * 4) : plane;
            cp_async16(smem_u32(tbuf + rr * TSTRIDE + COLOFF + ch * 4), src, ok);
        }
    }
}

__global__ __launch_bounds__(256, 2) void dwconv_kernel(
    const float* __restrict__ x, const float* __restrict__ bias,
    float* __restrict__ out) {
    __shared__ __align__(16) float tbuf[2][TROWS * TSTRIDE];
    __shared__ __align__(16) float wbuf[2][52];

    int tid = threadIdx.x;
    int cg = tid & 31, rg = tid >> 5;
    int col = cg * 4;
    int rbase = rg * 4;
    const int grid = gridDim.x;

    // zero the permanent halo columns of both buffers (once)
    for (int i = tid; i < 2 * TROWS * 8; i += 256) {
        int bufi = i >= TROWS * 8;
        int j = i - bufi * TROWS * 8;
        int rr = j >> 3;
        int k = j & 7;
        int cc = (k < 4) ? k : (128 + COLOFF + (k - 4));
        tbuf[bufi][rr * TSTRIDE + cc] = 0.f;
    }

    int t = blockIdx.x;
    if (t < NTILES) {
        load_tile_async(tbuf[0], wbuf[0], t, x, bias);
        cp_commit();
    }
    int cur = 0;

    for (; t < NTILES; t += grid) {
        cp_wait_all();
        __syncthreads();

        int tn = t + grid;
        if (tn < NTILES) {
            load_tile_async(tbuf[cur ^ 1], wbuf[cur ^ 1], tn, x, bias);
            cp_commit();
        }

        // ---- compute tile t from buf[cur] ----
        int bc = t >> 2;
        int r0 = (t & 3) * STRIP;

        float w[KK];
        {
            const float4* wv = reinterpret_cast<const float4*>(wbuf[cur]);
            #pragma unroll
            for (int q = 0; q < 12; q++) {
                float4 f = wv[q];
                w[4 * q + 0] = f.x; w[4 * q + 1] = f.y;
                w[4 * q + 2] = f.z; w[4 * q + 3] = f.w;
            }
            w[48] = wbuf[cur][48];
        }

        float bia = wbuf[cur][49];
        float acc[4][4];
        #pragma unroll
        for (int i = 0; i < 4; i++)
            #pragma unroll
            for (int j = 0; j < 4; j++) acc[i][j] = bia;

        const float* tile = tbuf[cur];
        #pragma unroll
        for (int ir = 0; ir < 4 + KS - 1; ir++) {     // 10 tile rows
            const float* tr = &tile[(rbase + ir) * TSTRIDE + col];
            float4 A = *reinterpret_cast<const float4*>(tr);
            float4 Bv = *reinterpret_cast<const float4*>(tr + 4);
            float4 Cv = *reinterpret_cast<const float4*>(tr + 8);
            float v[12] = {A.x, A.y, A.z, A.w,
                           Bv.x, Bv.y, Bv.z, Bv.w,
                           Cv.x, Cv.y, Cv.z, Cv.w};
            #pragma unroll
            for (int kh = 0; kh < KS; kh++) {
                int orr = ir - kh;
                if (orr >= 0 && orr < 4) {
                    #pragma unroll
                    for (int jj = 0; jj < 4; jj++) {
                        float s = acc[orr][jj];
                        #pragma unroll
                        for (int kw = 0; kw < KS; kw++)
                            s = fmaf(v[jj + kw + 1], w[kh * KS + kw], s);
                        acc[orr][jj] = s;
                    }
                }
            }
        }

        float* op = out + (size_t)bc * PLANE + (size_t)(r0 + rbase) * Ww + col;
        #pragma unroll
        for (int orr = 0; orr < 4; orr++)
            *reinterpret_cast<float4*>(op + (size_t)orr * Ww) =
                make_float4(acc[orr][0], acc[orr][1], acc[orr][2], acc[orr][3]);

        cur ^= 1;
    }
}

// ============================================================
// launch
// inputs: 0:x 1:w1 2:bn_gamma 3:bn_beta 4:bn_mean 5:bn_var 6:w2 7:b2 8:bias
// ============================================================
extern "C" void kernel_launch(void* const* d_in, const int* in_sizes, int n_in,
                              void* d_out, int out_size) {
    const float* x     = (const float*)d_in[0];
    const float* w1    = (const float*)d_in[1];
    const float* gamma = (const float*)d_in[2];
    const float* beta  = (const float*)d_in[3];
    const float* mean  = (const float*)d_in[4];
    const float* var   = (const float*)d_in[5];
    const float* w2    = (const float*)d_in[6];
    const float* b2    = (const float*)d_in[7];
    const float* bias  = (const float*)d_in[8];
    float* out = (float*)d_out;

    pool_kernel<<<B * DIM, 256>>>(x);
    dim3 g2((OUTW + W2_CHUNK - 1) / W2_CHUNK, B);
    gen_wdyn_kernel<<<g2, 128>>>(w1, gamma, beta, mean, var, w2, b2);
    dwconv_kernel<<<DW_GRID, 256>>>(x, bias, out);
}